// round 1
// baseline (speedup 1.0000x reference)
#include <cuda_runtime.h>
#include <cuda_bf16.h>
#include <float.h>
#include <math.h>

// Problem constants
#define HIDDEN 1024
#define HEADS  16
#define HDIM   64
#define B      2
#define T      2048
#define QKV3   (3 * HIDDEN)
#define BT     (B * T)        // 4096

// ---------------- scratch (static device globals; no allocation) -------------
__device__ float g_qkv[(size_t)BT * QKV3];                 // 4096 x 3072
__device__ float g_q[(size_t)B * HEADS * T * HDIM];        // [b,h,t,d]
__device__ float g_k[(size_t)B * HEADS * T * HDIM];
__device__ float g_v[(size_t)B * HEADS * T * HDIM];
__device__ float g_ctx[(size_t)BT * HIDDEN];               // [b,t, h*64+d]

// ---------------- SGEMM: C[M,N] = A[M,K] @ W[N,K]^T + bias[N] ----------------
// BM=BN=64, BK=16, 256 threads, 4x4 micro-tile per thread.
#define BM 64
#define BN 64
#define BK 16

__global__ __launch_bounds__(256) void sgemm_bias(
    const float* __restrict__ A, const float* __restrict__ W,
    const float* __restrict__ bias, float* __restrict__ C,
    int M, int N, int K)
{
    __shared__ float As[BK][BM];
    __shared__ float Ws[BK][BN];

    const int bm = blockIdx.y * BM;
    const int bn = blockIdx.x * BN;
    const int tid = threadIdx.x;
    const int tx = tid & 15;     // 0..15 (cols)
    const int ty = tid >> 4;     // 0..15 (rows)

    const int lr = tid >> 2;     // 0..63 row for loads
    const int lc = tid & 3;      // 0..3 float4 column for loads

    float acc[4][4];
#pragma unroll
    for (int i = 0; i < 4; i++)
#pragma unroll
        for (int j = 0; j < 4; j++) acc[i][j] = 0.f;

    const float* Ap = A + (size_t)(bm + lr) * K + lc * 4;
    const float* Wp = W + (size_t)(bn + lr) * K + lc * 4;

    for (int k0 = 0; k0 < K; k0 += BK) {
        float4 av = *(const float4*)(Ap + k0);
        float4 wv = *(const float4*)(Wp + k0);
        As[lc * 4 + 0][lr] = av.x; As[lc * 4 + 1][lr] = av.y;
        As[lc * 4 + 2][lr] = av.z; As[lc * 4 + 3][lr] = av.w;
        Ws[lc * 4 + 0][lr] = wv.x; Ws[lc * 4 + 1][lr] = wv.y;
        Ws[lc * 4 + 2][lr] = wv.z; Ws[lc * 4 + 3][lr] = wv.w;
        __syncthreads();

#pragma unroll
        for (int kk = 0; kk < BK; kk++) {
            float4 a = *(const float4*)&As[kk][ty * 4];
            float4 w = *(const float4*)&Ws[kk][tx * 4];
            acc[0][0] += a.x * w.x; acc[0][1] += a.x * w.y; acc[0][2] += a.x * w.z; acc[0][3] += a.x * w.w;
            acc[1][0] += a.y * w.x; acc[1][1] += a.y * w.y; acc[1][2] += a.y * w.z; acc[1][3] += a.y * w.w;
            acc[2][0] += a.z * w.x; acc[2][1] += a.z * w.y; acc[2][2] += a.z * w.z; acc[2][3] += a.z * w.w;
            acc[3][0] += a.w * w.x; acc[3][1] += a.w * w.y; acc[3][2] += a.w * w.z; acc[3][3] += a.w * w.w;
        }
        __syncthreads();
    }

    const int col = bn + tx * 4;
    float4 bb = *(const float4*)&bias[col];
#pragma unroll
    for (int i = 0; i < 4; i++) {
        int row = bm + ty * 4 + i;
        float4 r;
        r.x = acc[i][0] + bb.x; r.y = acc[i][1] + bb.y;
        r.z = acc[i][2] + bb.z; r.w = acc[i][3] + bb.w;
        *(float4*)&C[(size_t)row * N + col] = r;
    }
}

// ---------------- RoPE + reshape into [b,h,t,d] ------------------------------
// One thread per (b,t,h,i<32): handles q pair, k pair, v pair.
__global__ void rope_reshape(const float* __restrict__ qkv)
{
    int tid = blockIdx.x * blockDim.x + threadIdx.x;
    const int total = B * T * HEADS * 32;
    if (tid >= total) return;
    int i = tid & 31;
    int h = (tid >> 5) & (HEADS - 1);
    int t = (tid >> 9) & (T - 1);
    int b = tid >> 20;   // 32*16*2048 = 2^20

    const float expo = (float)(2 * i) / 64.0f;
    const float inv = 1.0f / powf(10000.0f, expo);
    const float ang = (float)t * inv;
    float c, s;
    __sincosf(ang, &s, &c);
    // use accurate versions to match reference closely
    c = cosf(ang); s = sinf(ang);

    const size_t base = (size_t)(b * T + t) * QKV3;
    const size_t ob = ((size_t)(b * HEADS + h) * T + t) * HDIM;

    float q1 = qkv[base + h * HDIM + i];
    float q2 = qkv[base + h * HDIM + i + 32];
    g_q[ob + i]      = q1 * c - q2 * s;
    g_q[ob + i + 32] = q1 * s + q2 * c;

    float k1 = qkv[base + HIDDEN + h * HDIM + i];
    float k2 = qkv[base + HIDDEN + h * HDIM + i + 32];
    g_k[ob + i]      = k1 * c - k2 * s;
    g_k[ob + i + 32] = k1 * s + k2 * c;

    g_v[ob + i]      = qkv[base + 2 * HIDDEN + h * HDIM + i];
    g_v[ob + i + 32] = qkv[base + 2 * HIDDEN + h * HDIM + i + 32];
}

// ---------------- Flash attention ------------------------------------------
// Block = (qtile of 64 rows, head, batch). 64 threads; thread t owns q-row t.
// Q row and O accumulator live in registers; K/V tiles staged in smem
// (broadcast reads across lanes -> conflict-free).
__global__ __launch_bounds__(64) void flash_attn(
    const int* __restrict__ ids, const long long* __restrict__ gidx, int n_g)
{
    const int lane = threadIdx.x;
    const int qt = blockIdx.x;
    const int h  = blockIdx.y;
    const int b  = blockIdx.z;
    const int qrow = qt * 64 + lane;

    // global-query flag for my row
    int myid = ids[b * T + qrow];
    bool gm = false;
    for (int g = 0; g < n_g; g++) gm |= (myid == (int)gidx[g]);

    __shared__ float Ks[64][64];
    __shared__ float Vs[64][64];
    __shared__ int anyg;
    if (lane == 0) anyg = 0;
    __syncthreads();
    if (gm) anyg = 1;
    __syncthreads();
    const int ktmax = anyg ? (T / 64 - 1) : qt;

    // load my q row
    float q[64];
    const float* qp = g_q + ((size_t)(b * HEADS + h) * T + qrow) * HDIM;
#pragma unroll
    for (int d4 = 0; d4 < 16; d4++) {
        float4 v = ((const float4*)qp)[d4];
        q[d4 * 4 + 0] = v.x; q[d4 * 4 + 1] = v.y;
        q[d4 * 4 + 2] = v.z; q[d4 * 4 + 3] = v.w;
    }

    float o[64];
#pragma unroll
    for (int d = 0; d < 64; d++) o[d] = 0.f;
    float m = -FLT_MAX, l = 0.f;

    const float* kbase = g_k + (size_t)(b * HEADS + h) * T * HDIM;
    const float* vbase = g_v + (size_t)(b * HEADS + h) * T * HDIM;

    for (int kt = 0; kt <= ktmax; kt++) {
        // stage K,V tiles (64x64), coalesced float4 loads
#pragma unroll
        for (int i = 0; i < 16; i++) {
            int idx = lane + i * 64;          // 0..1023
            int r = idx >> 4;                 // row 0..63
            int c4 = idx & 15;                // float4 col
            ((float4*)Ks[r])[c4] = ((const float4*)(kbase + (size_t)(kt * 64 + r) * HDIM))[c4];
            ((float4*)Vs[r])[c4] = ((const float4*)(vbase + (size_t)(kt * 64 + r) * HDIM))[c4];
        }
        __syncthreads();

        int jend;
        if (gm || kt < qt)      jend = 64;
        else if (kt == qt)      jend = lane + 1;
        else                    jend = 0;

        for (int j = 0; j < jend; j++) {
            float s = 0.f;
            const float4* kr = (const float4*)Ks[j];
#pragma unroll
            for (int d4 = 0; d4 < 16; d4++) {
                float4 kv = kr[d4];
                s += q[d4 * 4 + 0] * kv.x;
                s += q[d4 * 4 + 1] * kv.y;
                s += q[d4 * 4 + 2] * kv.z;
                s += q[d4 * 4 + 3] * kv.w;
            }
            s *= 0.125f;   // 1/sqrt(64)
            if (s > m) {
                float c = __expf(m - s);
                l *= c;
#pragma unroll
                for (int d = 0; d < 64; d++) o[d] *= c;
                m = s;
            }
            float p = __expf(s - m);
            l += p;
            const float4* vr = (const float4*)Vs[j];
#pragma unroll
            for (int d4 = 0; d4 < 16; d4++) {
                float4 vv = vr[d4];
                o[d4 * 4 + 0] += p * vv.x;
                o[d4 * 4 + 1] += p * vv.y;
                o[d4 * 4 + 2] += p * vv.z;
                o[d4 * 4 + 3] += p * vv.w;
            }
        }
        __syncthreads();
    }

    const float invl = 1.0f / l;
    float* outp = g_ctx + (size_t)(b * T + qrow) * HIDDEN + h * HDIM;
#pragma unroll
    for (int d4 = 0; d4 < 16; d4++) {
        float4 r;
        r.x = o[d4 * 4 + 0] * invl; r.y = o[d4 * 4 + 1] * invl;
        r.z = o[d4 * 4 + 2] * invl; r.w = o[d4 * 4 + 3] * invl;
        ((float4*)outp)[d4] = r;
    }
}

// ---------------- host launch ------------------------------------------------
extern "C" void kernel_launch(void* const* d_in, const int* in_sizes, int n_in,
                              void* d_out, int out_size)
{
    const float* x      = (const float*)d_in[0];
    const int*   ids    = (const int*)d_in[1];
    const float* qkv_w  = (const float*)d_in[2];
    const float* qkv_b  = (const float*)d_in[3];
    const float* out_w  = (const float*)d_in[4];
    const float* out_b  = (const float*)d_in[5];
    const long long* gi = (const long long*)d_in[6];
    const int n_g = in_sizes[6];
    float* out = (float*)d_out;

    float *p_qkv, *p_ctx;
    cudaGetSymbolAddress((void**)&p_qkv, g_qkv);
    cudaGetSymbolAddress((void**)&p_ctx, g_ctx);

    // 1) QKV projection: (4096,1024) @ (3072,1024)^T
    {
        dim3 grid(QKV3 / BN, BT / BM);
        sgemm_bias<<<grid, 256>>>(x, qkv_w, qkv_b, p_qkv, BT, QKV3, HIDDEN);
    }
    // 2) RoPE + reshape
    {
        int total = B * T * HEADS * 32;
        rope_reshape<<<(total + 255) / 256, 256>>>(p_qkv);
    }
    // 3) Flash attention
    {
        dim3 grid(T / 64, HEADS, B);
        flash_attn<<<grid, 64>>>(ids, gi, n_g);
    }
    // 4) Output projection: (4096,1024) @ (1024,1024)^T
    {
        dim3 grid(HIDDEN / BN, BT / BM);
        sgemm_bias<<<grid, 256>>>(p_ctx, out_w, out_b, out, BT, HIDDEN, HIDDEN);
    }
}

// round 4
// speedup vs baseline: 1.3401x; 1.3401x over previous
#include <cuda_runtime.h>
#include <cuda_bf16.h>
#include <mma.h>
#include <stdint.h>
#include <float.h>
#include <math.h>

using namespace nvcuda;

// Problem constants
#define HIDDEN 1024
#define HEADS  16
#define HDIM   64
#define B      2
#define T      2048
#define QKV3   (3 * HIDDEN)
#define BT     (B * T)        // 4096

// ---------------- scratch (static device globals; no allocation) -------------
__device__ float g_qkv[(size_t)BT * QKV3];                 // 4096 x 3072
__device__ float g_q[(size_t)B * HEADS * T * HDIM];        // [b,h,t,d]
__device__ float g_k[(size_t)B * HEADS * T * HDIM];
__device__ float g_v[(size_t)B * HEADS * T * HDIM];
__device__ float g_ctx[(size_t)BT * HIDDEN];               // [b,t, h*64+d]

__device__ __forceinline__ float f2tf32f(float x) {
    uint32_t u;
    asm("cvt.rna.tf32.f32 %0, %1;" : "=r"(u) : "f"(x));
    return __uint_as_float(u);
}

// ================== wmma TF32 GEMM: C[M,N] = A[M,K] @ W[N,K]^T + bias ========
// CTA tile 128x128, 256 threads (8 warps), warp tile 64x32 (4x2 frags of
// m16n16k8). K-chunks of 16, double-buffered smem, gmem prefetch into regs.
#define GPAD 20                       // smem row stride (floats)
#define SM_AS_OFF 0                   // As[2][128][GPAD]
#define SM_WS_OFF (2 * 128 * GPAD)    // Ws[2][128][GPAD]
#define SM_SCR_OFF (4 * 128 * GPAD)   // scratch[8][16*GPAD]
#define SM_FLOATS (SM_SCR_OFF + 8 * 16 * GPAD)
#define SM_BYTES (SM_FLOATS * 4)      // 51200 B

__global__ __launch_bounds__(256) void wmma_gemm(
    const float* __restrict__ A, const float* __restrict__ W,
    const float* __restrict__ bias, float* __restrict__ C,
    int Nt, int K)
{
    extern __shared__ float sm[];
    float* As = sm + SM_AS_OFF;
    float* Ws = sm + SM_WS_OFF;

    const int tid = threadIdx.x;
    const int wid = tid >> 5;
    const int lane = tid & 31;
    const int bm = blockIdx.y * 128;
    const int bn = blockIdx.x * 128;
    const int warpM = wid & 1;        // 0..1 -> 64-row slab
    const int warpN = wid >> 1;       // 0..3 -> 32-col slab
    float* scr = sm + SM_SCR_OFF + wid * (16 * GPAD);

    // loader indexing: 512 float4 per 128x16 tile, 2 per thread
    const int lrow0 = tid >> 2;           // 0..63
    const int lcol = (tid & 3) * 4;       // 0,4,8,12

    wmma::fragment<wmma::accumulator, 16, 16, 8, float> cfrag[4][2];
#pragma unroll
    for (int i = 0; i < 4; i++)
#pragma unroll
        for (int j = 0; j < 2; j++) wmma::fill_fragment(cfrag[i][j], 0.0f);

    const int NC = K / 16;

    // prologue: chunk 0 -> buffer 0
    {
#pragma unroll
        for (int t = 0; t < 2; t++) {
            int row = lrow0 + t * 64;
            float4 va = *(const float4*)(A + (size_t)(bm + row) * K + lcol);
            float4 vw = *(const float4*)(W + (size_t)(bn + row) * K + lcol);
            float* pa = As + row * GPAD + lcol;
            float* pw = Ws + row * GPAD + lcol;
            pa[0] = f2tf32f(va.x); pa[1] = f2tf32f(va.y); pa[2] = f2tf32f(va.z); pa[3] = f2tf32f(va.w);
            pw[0] = f2tf32f(vw.x); pw[1] = f2tf32f(vw.y); pw[2] = f2tf32f(vw.z); pw[3] = f2tf32f(vw.w);
        }
    }
    __syncthreads();

    for (int kc = 0; kc < NC; kc++) {
        const int b = kc & 1;
        const bool has_next = (kc + 1) < NC;
        float4 na[2], nw[2];
        if (has_next) {
            const int k0 = (kc + 1) * 16;
#pragma unroll
            for (int t = 0; t < 2; t++) {
                int row = lrow0 + t * 64;
                na[t] = *(const float4*)(A + (size_t)(bm + row) * K + k0 + lcol);
                nw[t] = *(const float4*)(W + (size_t)(bn + row) * K + k0 + lcol);
            }
        }

        const float* Ab = As + b * (128 * GPAD);
        const float* Wb = Ws + b * (128 * GPAD);
#pragma unroll
        for (int ks = 0; ks < 2; ks++) {
            wmma::fragment<wmma::matrix_a, 16, 16, 8, wmma::precision::tf32, wmma::row_major> af[4];
            wmma::fragment<wmma::matrix_b, 16, 16, 8, wmma::precision::tf32, wmma::col_major> bf[2];
#pragma unroll
            for (int i = 0; i < 4; i++)
                wmma::load_matrix_sync(af[i], Ab + (warpM * 64 + i * 16) * GPAD + ks * 8, GPAD);
#pragma unroll
            for (int j = 0; j < 2; j++)
                wmma::load_matrix_sync(bf[j], Wb + (warpN * 32 + j * 16) * GPAD + ks * 8, GPAD);
#pragma unroll
            for (int i = 0; i < 4; i++)
#pragma unroll
                for (int j = 0; j < 2; j++)
                    wmma::mma_sync(cfrag[i][j], af[i], bf[j], cfrag[i][j]);
        }

        if (has_next) {
            const int nb = 1 - b;
            float* pA = As + nb * (128 * GPAD);
            float* pW = Ws + nb * (128 * GPAD);
#pragma unroll
            for (int t = 0; t < 2; t++) {
                int row = lrow0 + t * 64;
                float* pa = pA + row * GPAD + lcol;
                float* pw = pW + row * GPAD + lcol;
                pa[0] = f2tf32f(na[t].x); pa[1] = f2tf32f(na[t].y); pa[2] = f2tf32f(na[t].z); pa[3] = f2tf32f(na[t].w);
                pw[0] = f2tf32f(nw[t].x); pw[1] = f2tf32f(nw[t].y); pw[2] = f2tf32f(nw[t].z); pw[3] = f2tf32f(nw[t].w);
            }
        }
        __syncthreads();
    }

    // epilogue: per-warp 16x16 staging + bias add
#pragma unroll
    for (int i = 0; i < 4; i++) {
#pragma unroll
        for (int j = 0; j < 2; j++) {
            wmma::store_matrix_sync(scr, cfrag[i][j], GPAD, wmma::mem_row_major);
            __syncwarp();
            const int gr = bm + warpM * 64 + i * 16;
            const int gc = bn + warpN * 32 + j * 16;
            const int r = lane >> 1;
            const int c0 = (lane & 1) * 8;
            float* cp = C + (size_t)(gr + r) * Nt + gc + c0;
            const float* sp = scr + r * GPAD + c0;
            float4 b0 = *(const float4*)(bias + gc + c0);
            float4 b1 = *(const float4*)(bias + gc + c0 + 4);
            float4 o0, o1;
            o0.x = sp[0] + b0.x; o0.y = sp[1] + b0.y; o0.z = sp[2] + b0.z; o0.w = sp[3] + b0.w;
            o1.x = sp[4] + b1.x; o1.y = sp[5] + b1.y; o1.z = sp[6] + b1.z; o1.w = sp[7] + b1.w;
            *(float4*)cp = o0;
            *(float4*)(cp + 4) = o1;
            __syncwarp();
        }
    }
}

// ---------------- RoPE + reshape into [b,h,t,d] ------------------------------
__global__ void rope_reshape(const float* __restrict__ qkv)
{
    int tid = blockIdx.x * blockDim.x + threadIdx.x;
    const int total = B * T * HEADS * 32;
    if (tid >= total) return;
    int i = tid & 31;
    int h = (tid >> 5) & (HEADS - 1);
    int t = (tid >> 9) & (T - 1);
    int b = tid >> 20;

    const float expo = (float)(2 * i) / 64.0f;
    const float inv = 1.0f / powf(10000.0f, expo);
    const float ang = (float)t * inv;
    float c = cosf(ang), s = sinf(ang);

    const size_t base = (size_t)(b * T + t) * QKV3;
    const size_t ob = ((size_t)(b * HEADS + h) * T + t) * HDIM;

    float q1 = qkv[base + h * HDIM + i];
    float q2 = qkv[base + h * HDIM + i + 32];
    g_q[ob + i]      = q1 * c - q2 * s;
    g_q[ob + i + 32] = q1 * s + q2 * c;

    float k1 = qkv[base + HIDDEN + h * HDIM + i];
    float k2 = qkv[base + HIDDEN + h * HDIM + i + 32];
    g_k[ob + i]      = k1 * c - k2 * s;
    g_k[ob + i + 32] = k1 * s + k2 * c;

    g_v[ob + i]      = qkv[base + 2 * HIDDEN + h * HDIM + i];
    g_v[ob + i + 32] = qkv[base + 2 * HIDDEN + h * HDIM + i + 32];
}

// ---------------- Flash attention (unchanged) --------------------------------
__global__ __launch_bounds__(64) void flash_attn(
    const int* __restrict__ ids, const long long* __restrict__ gidx, int n_g)
{
    const int lane = threadIdx.x;
    const int qt = blockIdx.x;
    const int h  = blockIdx.y;
    const int b  = blockIdx.z;
    const int qrow = qt * 64 + lane;

    int myid = ids[b * T + qrow];
    bool gm = false;
    for (int g = 0; g < n_g; g++) gm |= (myid == (int)gidx[g]);

    __shared__ float Ks[64][64];
    __shared__ float Vs[64][64];
    __shared__ int anyg;
    if (lane == 0) anyg = 0;
    __syncthreads();
    if (gm) anyg = 1;
    __syncthreads();
    const int ktmax = anyg ? (T / 64 - 1) : qt;

    float q[64];
    const float* qp = g_q + ((size_t)(b * HEADS + h) * T + qrow) * HDIM;
#pragma unroll
    for (int d4 = 0; d4 < 16; d4++) {
        float4 v = ((const float4*)qp)[d4];
        q[d4 * 4 + 0] = v.x; q[d4 * 4 + 1] = v.y;
        q[d4 * 4 + 2] = v.z; q[d4 * 4 + 3] = v.w;
    }

    float o[64];
#pragma unroll
    for (int d = 0; d < 64; d++) o[d] = 0.f;
    float m = -FLT_MAX, l = 0.f;

    const float* kbase = g_k + (size_t)(b * HEADS + h) * T * HDIM;
    const float* vbase = g_v + (size_t)(b * HEADS + h) * T * HDIM;

    for (int kt = 0; kt <= ktmax; kt++) {
#pragma unroll
        for (int i = 0; i < 16; i++) {
            int idx = lane + i * 64;
            int r = idx >> 4;
            int c4 = idx & 15;
            ((float4*)Ks[r])[c4] = ((const float4*)(kbase + (size_t)(kt * 64 + r) * HDIM))[c4];
            ((float4*)Vs[r])[c4] = ((const float4*)(vbase + (size_t)(kt * 64 + r) * HDIM))[c4];
        }
        __syncthreads();

        int jend;
        if (gm || kt < qt)      jend = 64;
        else if (kt == qt)      jend = lane + 1;
        else                    jend = 0;

        for (int j = 0; j < jend; j++) {
            float s = 0.f;
            const float4* kr = (const float4*)Ks[j];
#pragma unroll
            for (int d4 = 0; d4 < 16; d4++) {
                float4 kv = kr[d4];
                s += q[d4 * 4 + 0] * kv.x;
                s += q[d4 * 4 + 1] * kv.y;
                s += q[d4 * 4 + 2] * kv.z;
                s += q[d4 * 4 + 3] * kv.w;
            }
            s *= 0.125f;
            if (s > m) {
                float c = __expf(m - s);
                l *= c;
#pragma unroll
                for (int d = 0; d < 64; d++) o[d] *= c;
                m = s;
            }
            float p = __expf(s - m);
            l += p;
            const float4* vr = (const float4*)Vs[j];
#pragma unroll
            for (int d4 = 0; d4 < 16; d4++) {
                float4 vv = vr[d4];
                o[d4 * 4 + 0] += p * vv.x;
                o[d4 * 4 + 1] += p * vv.y;
                o[d4 * 4 + 2] += p * vv.z;
                o[d4 * 4 + 3] += p * vv.w;
            }
        }
        __syncthreads();
    }

    const float invl = 1.0f / l;
    float* outp = g_ctx + (size_t)(b * T + qrow) * HIDDEN + h * HDIM;
#pragma unroll
    for (int d4 = 0; d4 < 16; d4++) {
        float4 r;
        r.x = o[d4 * 4 + 0] * invl; r.y = o[d4 * 4 + 1] * invl;
        r.z = o[d4 * 4 + 2] * invl; r.w = o[d4 * 4 + 3] * invl;
        ((float4*)outp)[d4] = r;
    }
}

// ---------------- host launch ------------------------------------------------
extern "C" void kernel_launch(void* const* d_in, const int* in_sizes, int n_in,
                              void* d_out, int out_size)
{
    const float* x      = (const float*)d_in[0];
    const int*   ids    = (const int*)d_in[1];
    const float* qkv_w  = (const float*)d_in[2];
    const float* qkv_b  = (const float*)d_in[3];
    const float* out_w  = (const float*)d_in[4];
    const float* out_b  = (const float*)d_in[5];
    const long long* gi = (const long long*)d_in[6];
    const int n_g = in_sizes[6];
    float* out = (float*)d_out;

    float *p_qkv, *p_ctx;
    cudaGetSymbolAddress((void**)&p_qkv, g_qkv);
    cudaGetSymbolAddress((void**)&p_ctx, g_ctx);

    cudaFuncSetAttribute(wmma_gemm,
                         cudaFuncAttributeMaxDynamicSharedMemorySize, SM_BYTES);

    // 1) QKV projection: (4096,1024) @ (3072,1024)^T  -> wmma tf32
    {
        dim3 grid(QKV3 / 128, BT / 128);
        wmma_gemm<<<grid, 256, SM_BYTES>>>(x, qkv_w, qkv_b, p_qkv, QKV3, HIDDEN);
    }
    // 2) RoPE + reshape
    {
        int total = B * T * HEADS * 32;
        rope_reshape<<<(total + 255) / 256, 256>>>(p_qkv);
    }
    // 3) Flash attention
    {
        dim3 grid(T / 64, HEADS, B);
        flash_attn<<<grid, 64>>>(ids, gi, n_g);
    }
    // 4) Output projection: (4096,1024) @ (1024,1024)^T -> wmma tf32
    {
        dim3 grid(HIDDEN / 128, BT / 128);
        wmma_gemm<<<grid, 256, SM_BYTES>>>(p_ctx, out_w, out_b, out, HIDDEN, HIDDEN);
    }
}

// round 6
// speedup vs baseline: 2.7285x; 2.0360x over previous
#include <cuda_runtime.h>
#include <cuda_bf16.h>
#include <mma.h>
#include <stdint.h>
#include <float.h>
#include <math.h>

using namespace nvcuda;

// Problem constants
#define HIDDEN 1024
#define HEADS  16
#define HDIM   64
#define B      2
#define T      2048
#define QKV3   (3 * HIDDEN)
#define BT     (B * T)        // 4096

// ---------------- scratch (static device globals; no allocation) -------------
__device__ float g_qkv[(size_t)BT * QKV3];                 // 4096 x 3072
__device__ float g_q[(size_t)B * HEADS * T * HDIM];        // [b,h,t,d]
__device__ float g_k[(size_t)B * HEADS * T * HDIM];
__device__ float g_v[(size_t)B * HEADS * T * HDIM];
__device__ float g_ctx[(size_t)BT * HIDDEN];               // [b,t, h*64+d]

__device__ __forceinline__ float f2tf32f(float x) {
    uint32_t u;
    asm("cvt.rna.tf32.f32 %0, %1;" : "=r"(u) : "f"(x));
    return __uint_as_float(u);
}

// raw tf32 mma: D(16x8) += A(16x8) * B(8x8); acc regs in-place
__device__ __forceinline__ void mma_tf32(float* c, const float* a, float b0, float b1) {
    asm volatile(
        "mma.sync.aligned.m16n8k8.row.col.f32.tf32.tf32.f32 "
        "{%0,%1,%2,%3}, {%4,%5,%6,%7}, {%8,%9}, {%0,%1,%2,%3};"
        : "+f"(c[0]), "+f"(c[1]), "+f"(c[2]), "+f"(c[3])
        : "r"(__float_as_uint(a[0])), "r"(__float_as_uint(a[1])),
          "r"(__float_as_uint(a[2])), "r"(__float_as_uint(a[3])),
          "r"(__float_as_uint(b0)), "r"(__float_as_uint(b1)));
}

// ================== wmma TF32 GEMM: C[M,N] = A[M,K] @ W[N,K]^T + bias ========
#define GPAD 20
#define SM_AS_OFF 0
#define SM_WS_OFF (2 * 128 * GPAD)
#define SM_SCR_OFF (4 * 128 * GPAD)
#define SM_FLOATS (SM_SCR_OFF + 8 * 16 * GPAD)
#define SM_BYTES (SM_FLOATS * 4)

__global__ __launch_bounds__(256) void wmma_gemm(
    const float* __restrict__ A, const float* __restrict__ W,
    const float* __restrict__ bias, float* __restrict__ C,
    int Nt, int K)
{
    extern __shared__ float sm[];
    float* As = sm + SM_AS_OFF;
    float* Ws = sm + SM_WS_OFF;

    const int tid = threadIdx.x;
    const int wid = tid >> 5;
    const int lane = tid & 31;
    const int bm = blockIdx.y * 128;
    const int bn = blockIdx.x * 128;
    const int warpM = wid & 1;
    const int warpN = wid >> 1;
    float* scr = sm + SM_SCR_OFF + wid * (16 * GPAD);

    const int lrow0 = tid >> 2;
    const int lcol = (tid & 3) * 4;

    wmma::fragment<wmma::accumulator, 16, 16, 8, float> cfrag[4][2];
#pragma unroll
    for (int i = 0; i < 4; i++)
#pragma unroll
        for (int j = 0; j < 2; j++) wmma::fill_fragment(cfrag[i][j], 0.0f);

    const int NC = K / 16;

    {
#pragma unroll
        for (int t = 0; t < 2; t++) {
            int row = lrow0 + t * 64;
            float4 va = *(const float4*)(A + (size_t)(bm + row) * K + lcol);
            float4 vw = *(const float4*)(W + (size_t)(bn + row) * K + lcol);
            float* pa = As + row * GPAD + lcol;
            float* pw = Ws + row * GPAD + lcol;
            pa[0] = f2tf32f(va.x); pa[1] = f2tf32f(va.y); pa[2] = f2tf32f(va.z); pa[3] = f2tf32f(va.w);
            pw[0] = f2tf32f(vw.x); pw[1] = f2tf32f(vw.y); pw[2] = f2tf32f(vw.z); pw[3] = f2tf32f(vw.w);
        }
    }
    __syncthreads();

    for (int kc = 0; kc < NC; kc++) {
        const int b = kc & 1;
        const bool has_next = (kc + 1) < NC;
        float4 na[2], nw[2];
        if (has_next) {
            const int k0 = (kc + 1) * 16;
#pragma unroll
            for (int t = 0; t < 2; t++) {
                int row = lrow0 + t * 64;
                na[t] = *(const float4*)(A + (size_t)(bm + row) * K + k0 + lcol);
                nw[t] = *(const float4*)(W + (size_t)(bn + row) * K + k0 + lcol);
            }
        }

        const float* Ab = As + b * (128 * GPAD);
        const float* Wb = Ws + b * (128 * GPAD);
#pragma unroll
        for (int ks = 0; ks < 2; ks++) {
            wmma::fragment<wmma::matrix_a, 16, 16, 8, wmma::precision::tf32, wmma::row_major> af[4];
            wmma::fragment<wmma::matrix_b, 16, 16, 8, wmma::precision::tf32, wmma::col_major> bf[2];
#pragma unroll
            for (int i = 0; i < 4; i++)
                wmma::load_matrix_sync(af[i], Ab + (warpM * 64 + i * 16) * GPAD + ks * 8, GPAD);
#pragma unroll
            for (int j = 0; j < 2; j++)
                wmma::load_matrix_sync(bf[j], Wb + (warpN * 32 + j * 16) * GPAD + ks * 8, GPAD);
#pragma unroll
            for (int i = 0; i < 4; i++)
#pragma unroll
                for (int j = 0; j < 2; j++)
                    wmma::mma_sync(cfrag[i][j], af[i], bf[j], cfrag[i][j]);
        }

        if (has_next) {
            const int nb = 1 - b;
            float* pA = As + nb * (128 * GPAD);
            float* pW = Ws + nb * (128 * GPAD);
#pragma unroll
            for (int t = 0; t < 2; t++) {
                int row = lrow0 + t * 64;
                float* pa = pA + row * GPAD + lcol;
                float* pw = pW + row * GPAD + lcol;
                pa[0] = f2tf32f(na[t].x); pa[1] = f2tf32f(na[t].y); pa[2] = f2tf32f(na[t].z); pa[3] = f2tf32f(na[t].w);
                pw[0] = f2tf32f(nw[t].x); pw[1] = f2tf32f(nw[t].y); pw[2] = f2tf32f(nw[t].z); pw[3] = f2tf32f(nw[t].w);
            }
        }
        __syncthreads();
    }

#pragma unroll
    for (int i = 0; i < 4; i++) {
#pragma unroll
        for (int j = 0; j < 2; j++) {
            wmma::store_matrix_sync(scr, cfrag[i][j], GPAD, wmma::mem_row_major);
            __syncwarp();
            const int gr = bm + warpM * 64 + i * 16;
            const int gc = bn + warpN * 32 + j * 16;
            const int r = lane >> 1;
            const int c0 = (lane & 1) * 8;
            float* cp = C + (size_t)(gr + r) * Nt + gc + c0;
            const float* sp = scr + r * GPAD + c0;
            float4 b0 = *(const float4*)(bias + gc + c0);
            float4 b1 = *(const float4*)(bias + gc + c0 + 4);
            float4 o0, o1;
            o0.x = sp[0] + b0.x; o0.y = sp[1] + b0.y; o0.z = sp[2] + b0.z; o0.w = sp[3] + b0.w;
            o1.x = sp[4] + b1.x; o1.y = sp[5] + b1.y; o1.z = sp[6] + b1.z; o1.w = sp[7] + b1.w;
            *(float4*)cp = o0;
            *(float4*)(cp + 4) = o1;
            __syncwarp();
        }
    }
}

// ---------------- RoPE + reshape into [b,h,t,d] ------------------------------
__global__ void rope_reshape(const float* __restrict__ qkv)
{
    int tid = blockIdx.x * blockDim.x + threadIdx.x;
    const int total = B * T * HEADS * 32;
    if (tid >= total) return;
    int i = tid & 31;
    int h = (tid >> 5) & (HEADS - 1);
    int t = (tid >> 9) & (T - 1);
    int b = tid >> 20;

    const float expo = (float)(2 * i) / 64.0f;
    const float inv = 1.0f / powf(10000.0f, expo);
    const float ang = (float)t * inv;
    float c = cosf(ang), s = sinf(ang);

    const size_t base = (size_t)(b * T + t) * QKV3;
    const size_t ob = ((size_t)(b * HEADS + h) * T + t) * HDIM;

    float q1 = qkv[base + h * HDIM + i];
    float q2 = qkv[base + h * HDIM + i + 32];
    g_q[ob + i]      = q1 * c - q2 * s;
    g_q[ob + i + 32] = q1 * s + q2 * c;

    float k1 = qkv[base + HIDDEN + h * HDIM + i];
    float k2 = qkv[base + HIDDEN + h * HDIM + i + 32];
    g_k[ob + i]      = k1 * c - k2 * s;
    g_k[ob + i + 32] = k1 * s + k2 * c;

    g_v[ob + i]      = qkv[base + 2 * HIDDEN + h * HDIM + i];
    g_v[ob + i + 32] = qkv[base + 2 * HIDDEN + h * HDIM + i + 32];
}

// ================== tensor-core flash attention ==============================
// CTA: 128 q rows x (head,batch); 4 warps; warp w owns rows [w*32, w*32+32).
// KV tile = 64 keys. S and O via mma.m16n8k8.tf32; softmax in registers.
#define KPAD 68
#define VPAD 72
#define PPAD 68
#define FSM_K 0
#define FSM_V (64 * KPAD)
#define FSM_P (FSM_V + 64 * VPAD)
#define FSM_FLOATS (FSM_P + 4 * 32 * PPAD)
#define FSM_BYTES (FSM_FLOATS * 4)

__global__ __launch_bounds__(128) void flash_mma(
    const int* __restrict__ ids, const long long* __restrict__ gidx, int n_g)
{
    extern __shared__ float fsm[];
    float* Ksm = fsm + FSM_K;
    float* Vsm = fsm + FSM_V;
    float* Psm = fsm + FSM_P;
    __shared__ int s_anyg;

    const int tid = threadIdx.x;
    const int w = tid >> 5;
    const int lane = tid & 31;
    const int g = lane >> 2;      // group id (row within frag)
    const int t = lane & 3;       // thread in group
    const int qb = blockIdx.x;
    const int h = blockIdx.y;
    const int b = blockIdx.z;
    const int bh = b * HEADS + h;
    const int qrow0 = qb * 128;

    // ---- global-query flags ----
    if (tid == 0) s_anyg = 0;
    __syncthreads();
    {
        int myid = ids[b * T + qrow0 + tid];
        bool myg = false;
        for (int i = 0; i < n_g; i++) myg |= (myid == (int)gidx[i]);
        if (myg) s_anyg = 1;
    }
    // per-warp 32-row mask: bit r <-> row w*32+r
    unsigned gmask;
    {
        int rid = ids[b * T + qrow0 + w * 32 + lane];
        bool rg = false;
        for (int i = 0; i < n_g; i++) rg |= (rid == (int)gidx[i]);
        gmask = __ballot_sync(0xffffffffu, rg);
    }
    __syncthreads();
    const int ktmax = s_anyg ? (T / 64 - 1) : (2 * qb + 1);

    // ---- load Q fragments (kept in registers) ----
    float q[2][8][4];
    {
        const float* Qb = g_q + ((size_t)bh * T + qrow0 + w * 32) * HDIM;
#pragma unroll
        for (int rb = 0; rb < 2; rb++)
#pragma unroll
            for (int ks = 0; ks < 8; ks++) {
                q[rb][ks][0] = f2tf32f(Qb[(rb * 16 + g) * 64 + ks * 8 + t]);
                q[rb][ks][1] = f2tf32f(Qb[(rb * 16 + 8 + g) * 64 + ks * 8 + t]);
                q[rb][ks][2] = f2tf32f(Qb[(rb * 16 + g) * 64 + ks * 8 + t + 4]);
                q[rb][ks][3] = f2tf32f(Qb[(rb * 16 + 8 + g) * 64 + ks * 8 + t + 4]);
            }
    }

    float o[2][8][4];
#pragma unroll
    for (int rb = 0; rb < 2; rb++)
#pragma unroll
        for (int f = 0; f < 8; f++)
#pragma unroll
            for (int e = 0; e < 4; e++) o[rb][f][e] = 0.f;
    float m_[2][2], l_[2][2];
#pragma unroll
    for (int rb = 0; rb < 2; rb++)
#pragma unroll
        for (int hh = 0; hh < 2; hh++) { m_[rb][hh] = -1e30f; l_[rb][hh] = 0.f; }

    const float* Kgb = g_k + (size_t)bh * T * HDIM;
    const float* Vgb = g_v + (size_t)bh * T * HDIM;

    for (int kt = 0; kt <= ktmax; kt++) {
        __syncthreads();
        // ---- cooperative K/V tile load (tf32-rounded) ----
#pragma unroll
        for (int j = 0; j < 8; j++) {
            int i = tid + j * 128;           // 0..1023
            int r = i >> 4;
            int c4 = i & 15;
            float4 kv = *(const float4*)(Kgb + (size_t)(kt * 64 + r) * 64 + c4 * 4);
            float4 vv = *(const float4*)(Vgb + (size_t)(kt * 64 + r) * 64 + c4 * 4);
            float* kp = Ksm + r * KPAD + c4 * 4;
            kp[0] = f2tf32f(kv.x); kp[1] = f2tf32f(kv.y); kp[2] = f2tf32f(kv.z); kp[3] = f2tf32f(kv.w);
            float* vp = Vsm + r * VPAD + c4 * 4;
            vp[0] = f2tf32f(vv.x); vp[1] = f2tf32f(vv.y); vp[2] = f2tf32f(vv.z); vp[3] = f2tf32f(vv.w);
        }
        __syncthreads();

        // ---- S = Q @ K^T ----
        float s[2][8][4];
#pragma unroll
        for (int rb = 0; rb < 2; rb++)
#pragma unroll
            for (int f = 0; f < 8; f++)
#pragma unroll
                for (int e = 0; e < 4; e++) s[rb][f][e] = 0.f;
#pragma unroll
        for (int ks = 0; ks < 8; ks++) {
#pragma unroll
            for (int f = 0; f < 8; f++) {
                float b0 = Ksm[(f * 8 + g) * KPAD + ks * 8 + t];
                float b1 = Ksm[(f * 8 + g) * KPAD + ks * 8 + t + 4];
                mma_tf32(s[0][f], q[0][ks], b0, b1);
                mma_tf32(s[1][f], q[1][ks], b0, b1);
            }
        }

        // ---- masked online softmax (registers) ----
#pragma unroll
        for (int rb = 0; rb < 2; rb++) {
#pragma unroll
            for (int hh = 0; hh < 2; hh++) {
                const int rloc = rb * 16 + hh * 8 + g;
                const int grow = qrow0 + w * 32 + rloc;
                const bool rowg = (gmask >> rloc) & 1u;
                float pv[16];
                float mx = -1e30f;
                const bool fullok = (kt * 64 + 63 <= grow) || rowg;
#pragma unroll
                for (int f = 0; f < 8; f++) {
#pragma unroll
                    for (int e = 0; e < 2; e++) {
                        float sv = s[rb][f][hh * 2 + e] * 0.125f;
                        if (!fullok) {
                            int col = kt * 64 + f * 8 + 2 * t + e;
                            if (col > grow) sv = -1e30f;
                        }
                        pv[f * 2 + e] = sv;
                        mx = fmaxf(mx, sv);
                    }
                }
                mx = fmaxf(mx, __shfl_xor_sync(0xffffffffu, mx, 1));
                mx = fmaxf(mx, __shfl_xor_sync(0xffffffffu, mx, 2));
                float mold = m_[rb][hh];
                float mnew = fmaxf(mold, mx);
                float corr = __expf(mold - mnew);
                float lsum = 0.f;
#pragma unroll
                for (int i = 0; i < 16; i++) {
                    float p = __expf(pv[i] - mnew);
                    pv[i] = p;
                    lsum += p;
                }
                lsum += __shfl_xor_sync(0xffffffffu, lsum, 1);
                lsum += __shfl_xor_sync(0xffffffffu, lsum, 2);
                m_[rb][hh] = mnew;
                l_[rb][hh] = l_[rb][hh] * corr + lsum;
#pragma unroll
                for (int f = 0; f < 8; f++) {
                    o[rb][f][hh * 2] *= corr;
                    o[rb][f][hh * 2 + 1] *= corr;
                }
                float* prow = Psm + w * (32 * PPAD) + rloc * PPAD;
#pragma unroll
                for (int f = 0; f < 8; f++) {
                    float2 pr;
                    pr.x = f2tf32f(pv[f * 2]);
                    pr.y = f2tf32f(pv[f * 2 + 1]);
                    *(float2*)(prow + f * 8 + 2 * t) = pr;
                }
            }
        }
        __syncwarp();

        // ---- O += P @ V ----
        const float* pb = Psm + w * (32 * PPAD);
#pragma unroll
        for (int ks = 0; ks < 8; ks++) {
            float ap[2][4];
#pragma unroll
            for (int rb = 0; rb < 2; rb++) {
                ap[rb][0] = pb[(rb * 16 + g) * PPAD + ks * 8 + t];
                ap[rb][1] = pb[(rb * 16 + 8 + g) * PPAD + ks * 8 + t];
                ap[rb][2] = pb[(rb * 16 + g) * PPAD + ks * 8 + t + 4];
                ap[rb][3] = pb[(rb * 16 + 8 + g) * PPAD + ks * 8 + t + 4];
            }
#pragma unroll
            for (int f = 0; f < 8; f++) {
                float b0 = Vsm[(ks * 8 + t) * VPAD + f * 8 + g];
                float b1 = Vsm[(ks * 8 + t + 4) * VPAD + f * 8 + g];
                mma_tf32(o[0][f], ap[0], b0, b1);
                mma_tf32(o[1][f], ap[1], b0, b1);
            }
        }
    }

    // ---- epilogue: normalize + write ----
#pragma unroll
    for (int rb = 0; rb < 2; rb++) {
#pragma unroll
        for (int hh = 0; hh < 2; hh++) {
            float invl = 1.0f / l_[rb][hh];
            int trow = qrow0 + w * 32 + rb * 16 + hh * 8 + g;
            float* op = g_ctx + ((size_t)b * T + trow) * HIDDEN + h * 64;
#pragma unroll
            for (int f = 0; f < 8; f++) {
                float2 r;
                r.x = o[rb][f][hh * 2] * invl;
                r.y = o[rb][f][hh * 2 + 1] * invl;
                *(float2*)(op + f * 8 + 2 * t) = r;
            }
        }
    }
}

// ---------------- host launch ------------------------------------------------
extern "C" void kernel_launch(void* const* d_in, const int* in_sizes, int n_in,
                              void* d_out, int out_size)
{
    const float* x      = (const float*)d_in[0];
    const int*   ids    = (const int*)d_in[1];
    const float* qkv_w  = (const float*)d_in[2];
    const float* qkv_b  = (const float*)d_in[3];
    const float* out_w  = (const float*)d_in[4];
    const float* out_b  = (const float*)d_in[5];
    const long long* gi = (const long long*)d_in[6];
    const int n_g = in_sizes[6];
    float* out = (float*)d_out;

    float *p_qkv, *p_ctx;
    cudaGetSymbolAddress((void**)&p_qkv, g_qkv);
    cudaGetSymbolAddress((void**)&p_ctx, g_ctx);

    cudaFuncSetAttribute(wmma_gemm,
                         cudaFuncAttributeMaxDynamicSharedMemorySize, SM_BYTES);
    cudaFuncSetAttribute(flash_mma,
                         cudaFuncAttributeMaxDynamicSharedMemorySize, FSM_BYTES);

    // 1) QKV projection
    {
        dim3 grid(QKV3 / 128, BT / 128);
        wmma_gemm<<<grid, 256, SM_BYTES>>>(x, qkv_w, qkv_b, p_qkv, QKV3, HIDDEN);
    }
    // 2) RoPE + reshape
    {
        int total = B * T * HEADS * 32;
        rope_reshape<<<(total + 255) / 256, 256>>>(p_qkv);
    }
    // 3) Flash attention (tensor cores)
    {
        dim3 grid(T / 128, HEADS, B);
        flash_mma<<<grid, 128, FSM_BYTES>>>(ids, gi, n_g);
    }
    // 4) Output projection
    {
        dim3 grid(HIDDEN / 128, BT / 128);
        wmma_gemm<<<grid, 256, SM_BYTES>>>(p_ctx, out_w, out_b, out, HIDDEN, HIDDEN);
    }
}

// round 7
// speedup vs baseline: 3.6515x; 1.3383x over previous
#include <cuda_runtime.h>
#include <cuda_bf16.h>
#include <stdint.h>
#include <float.h>
#include <math.h>

// Problem constants
#define HIDDEN 1024
#define HEADS  16
#define HDIM   64
#define B      2
#define T      2048
#define QKV3   (3 * HIDDEN)
#define BT     (B * T)        // 4096

// ---------------- scratch (static device globals; no allocation) -------------
__device__ float g_qkv[(size_t)BT * QKV3];                 // 4096 x 3072
__device__ float g_q[(size_t)B * HEADS * T * HDIM];        // [b,h,t,d]
__device__ float g_k[(size_t)B * HEADS * T * HDIM];
__device__ float g_v[(size_t)B * HEADS * T * HDIM];
__device__ float g_ctx[(size_t)BT * HIDDEN];               // [b,t, h*64+d] (tf32-rounded)
__device__ float g_xr[(size_t)BT * HIDDEN];                // tf32-rounded x
__device__ float g_wqkv[(size_t)QKV3 * HIDDEN];            // tf32-rounded qkv_w
__device__ float g_wout[(size_t)HIDDEN * HIDDEN];          // tf32-rounded out_w

__device__ __forceinline__ float f2tf32f(float x) {
    uint32_t u;
    asm("cvt.rna.tf32.f32 %0, %1;" : "=r"(u) : "f"(x));
    return __uint_as_float(u);
}

__device__ __forceinline__ uint32_t smem_u32(const void* p) {
    uint32_t a;
    asm("{ .reg .u64 t; cvta.to.shared.u64 t, %1; cvt.u32.u64 %0, t; }"
        : "=r"(a) : "l"(p));
    return a;
}

#define CP_ASYNC16(dst, src) \
    asm volatile("cp.async.ca.shared.global [%0], [%1], 16;" :: "r"(dst), "l"(src))
#define CP_COMMIT() asm volatile("cp.async.commit_group;" ::: "memory")
#define CP_WAIT0() asm volatile("cp.async.wait_group 0;" ::: "memory")
#define CP_WAIT1() asm volatile("cp.async.wait_group 1;" ::: "memory")

// raw tf32 mma: D(16x8) += A(16x8) * B(8x8); acc regs in-place
__device__ __forceinline__ void mma_tf32(float* c, const float* a, float b0, float b1) {
    asm volatile(
        "mma.sync.aligned.m16n8k8.row.col.f32.tf32.tf32.f32 "
        "{%0,%1,%2,%3}, {%4,%5,%6,%7}, {%8,%9}, {%0,%1,%2,%3};"
        : "+f"(c[0]), "+f"(c[1]), "+f"(c[2]), "+f"(c[3])
        : "r"(__float_as_uint(a[0])), "r"(__float_as_uint(a[1])),
          "r"(__float_as_uint(a[2])), "r"(__float_as_uint(a[3])),
          "r"(__float_as_uint(b0)), "r"(__float_as_uint(b1)));
}

// ---------------- tf32 pre-round pass ----------------------------------------
__global__ void round_tf32(const float* __restrict__ src, float* __restrict__ dst, int n4)
{
    int i = blockIdx.x * blockDim.x + threadIdx.x;
    if (i >= n4) return;
    float4 v = ((const float4*)src)[i];
    float4 r;
    r.x = f2tf32f(v.x); r.y = f2tf32f(v.y); r.z = f2tf32f(v.z); r.w = f2tf32f(v.w);
    ((float4*)dst)[i] = r;
}

// ========= raw-mma TF32 GEMM: C[M,N] = A[M,K] @ W[N,K]^T + bias ==============
// Inputs MUST be pre-rounded to tf32. CTA 128x128, 8 warps (warp 64x32),
// BK=32 chunks, 2-stage cp.async double buffer.
#define BKC 32
#define ASTR 36
#define TSM_W_OFF (2 * 128 * ASTR)
#define TSM_FLOATS (4 * 128 * ASTR)
#define TSM_BYTES (TSM_FLOATS * 4)   // 73728

__global__ __launch_bounds__(256, 2) void mma_gemm(
    const float* __restrict__ A, const float* __restrict__ W,
    const float* __restrict__ bias, float* __restrict__ C,
    int Nt, int K)
{
    extern __shared__ float sm[];
    float* As = sm;
    float* Ws = sm + TSM_W_OFF;

    const int tid = threadIdx.x;
    const int wid = tid >> 5;
    const int lane = tid & 31;
    const int g = lane >> 2;
    const int t = lane & 3;
    const int bm = blockIdx.y * 128;
    const int bn = blockIdx.x * 128;
    const int warpM = wid & 1;        // 0..1 -> 64-row slab
    const int warpN = wid >> 1;       // 0..3 -> 32-col slab

    // loader mapping: row = tid>>1 (0..127), half = tid&1; 4 quads of 16B each
    const int lrow = tid >> 1;
    const int lq0 = (tid & 1) * 4;    // quad index base (each quad = 16B = 4 floats)

    const uint32_t sa = smem_u32(As);
    const uint32_t sw = smem_u32(Ws);
    const float* gA = A + (size_t)(bm + lrow) * K + lq0 * 4;
    const float* gW = W + (size_t)(bn + lrow) * K + lq0 * 4;
    const uint32_t da0 = sa + (lrow * ASTR + lq0 * 4) * 4;
    const uint32_t dw0 = sw + (lrow * ASTR + lq0 * 4) * 4;

    float acc[4][4][4];
#pragma unroll
    for (int mi = 0; mi < 4; mi++)
#pragma unroll
        for (int ni = 0; ni < 4; ni++)
#pragma unroll
            for (int e = 0; e < 4; e++) acc[mi][ni][e] = 0.f;

    const int NC = K / BKC;           // 32

    // prologue: chunk 0 -> buffer 0
#pragma unroll
    for (int q = 0; q < 4; q++) {
        CP_ASYNC16(da0 + q * 16, gA + q * 4);
        CP_ASYNC16(dw0 + q * 16, gW + q * 4);
    }
    CP_COMMIT();

    for (int c = 0; c < NC; c++) {
        const int buf = c & 1;
        if (c + 1 < NC) {
            const int nb = 1 - buf;
            const uint32_t dA = da0 + nb * (128 * ASTR * 4);
            const uint32_t dW = dw0 + nb * (128 * ASTR * 4);
            const float* pA = gA + (c + 1) * BKC;
            const float* pW = gW + (c + 1) * BKC;
#pragma unroll
            for (int q = 0; q < 4; q++) {
                CP_ASYNC16(dA + q * 16, pA + q * 4);
                CP_ASYNC16(dW + q * 16, pW + q * 4);
            }
            CP_COMMIT();
            CP_WAIT1();
        } else {
            CP_WAIT0();
        }
        __syncthreads();

        const float* Ab = As + buf * (128 * ASTR) + (warpM * 64) * ASTR;
        const float* Wb = Ws + buf * (128 * ASTR) + (warpN * 32) * ASTR;
#pragma unroll
        for (int ks = 0; ks < 4; ks++) {
            const int k0 = ks * 8;
            float bf[4][2];
#pragma unroll
            for (int ni = 0; ni < 4; ni++) {
                bf[ni][0] = Wb[(ni * 8 + g) * ASTR + k0 + t];
                bf[ni][1] = Wb[(ni * 8 + g) * ASTR + k0 + t + 4];
            }
#pragma unroll
            for (int mi = 0; mi < 4; mi++) {
                float af[4];
                af[0] = Ab[(mi * 16 + g) * ASTR + k0 + t];
                af[1] = Ab[(mi * 16 + 8 + g) * ASTR + k0 + t];
                af[2] = Ab[(mi * 16 + g) * ASTR + k0 + t + 4];
                af[3] = Ab[(mi * 16 + 8 + g) * ASTR + k0 + t + 4];
#pragma unroll
                for (int ni = 0; ni < 4; ni++)
                    mma_tf32(acc[mi][ni], af, bf[ni][0], bf[ni][1]);
            }
        }
        __syncthreads();
    }

    // epilogue: direct float2 stores + bias
#pragma unroll
    for (int mi = 0; mi < 4; mi++) {
        const int row0 = bm + warpM * 64 + mi * 16 + g;
#pragma unroll
        for (int ni = 0; ni < 4; ni++) {
            const int col = bn + warpN * 32 + ni * 8 + 2 * t;
            const float bx = bias[col], by = bias[col + 1];
            float2 r0, r1;
            r0.x = acc[mi][ni][0] + bx; r0.y = acc[mi][ni][1] + by;
            r1.x = acc[mi][ni][2] + bx; r1.y = acc[mi][ni][3] + by;
            *(float2*)(C + (size_t)row0 * Nt + col) = r0;
            *(float2*)(C + (size_t)(row0 + 8) * Nt + col) = r1;
        }
    }
}

// ---------------- RoPE + reshape into [b,h,t,d] ------------------------------
__global__ void rope_reshape(const float* __restrict__ qkv)
{
    int tid = blockIdx.x * blockDim.x + threadIdx.x;
    const int total = B * T * HEADS * 32;
    if (tid >= total) return;
    int i = tid & 31;
    int h = (tid >> 5) & (HEADS - 1);
    int t = (tid >> 9) & (T - 1);
    int b = tid >> 20;

    const float expo = (float)(2 * i) / 64.0f;
    const float inv = 1.0f / powf(10000.0f, expo);
    const float ang = (float)t * inv;
    float c = cosf(ang), s = sinf(ang);

    const size_t base = (size_t)(b * T + t) * QKV3;
    const size_t ob = ((size_t)(b * HEADS + h) * T + t) * HDIM;

    float q1 = qkv[base + h * HDIM + i];
    float q2 = qkv[base + h * HDIM + i + 32];
    g_q[ob + i]      = q1 * c - q2 * s;
    g_q[ob + i + 32] = q1 * s + q2 * c;

    float k1 = qkv[base + HIDDEN + h * HDIM + i];
    float k2 = qkv[base + HIDDEN + h * HDIM + i + 32];
    g_k[ob + i]      = k1 * c - k2 * s;
    g_k[ob + i + 32] = k1 * s + k2 * c;

    g_v[ob + i]      = qkv[base + 2 * HIDDEN + h * HDIM + i];
    g_v[ob + i + 32] = qkv[base + 2 * HIDDEN + h * HDIM + i + 32];
}

// ================== tensor-core flash attention ==============================
#define KPAD 68
#define VPAD 72
#define PPAD 68
#define FSM_K 0
#define FSM_V (64 * KPAD)
#define FSM_P (FSM_V + 64 * VPAD)
#define FSM_FLOATS (FSM_P + 4 * 32 * PPAD)
#define FSM_BYTES (FSM_FLOATS * 4)

__global__ __launch_bounds__(128) void flash_mma(
    const int* __restrict__ ids, const long long* __restrict__ gidx, int n_g)
{
    extern __shared__ float fsm[];
    float* Ksm = fsm + FSM_K;
    float* Vsm = fsm + FSM_V;
    float* Psm = fsm + FSM_P;
    __shared__ int s_anyg;

    const int tid = threadIdx.x;
    const int w = tid >> 5;
    const int lane = tid & 31;
    const int g = lane >> 2;
    const int t = lane & 3;
    const int qb = blockIdx.x;
    const int h = blockIdx.y;
    const int b = blockIdx.z;
    const int bh = b * HEADS + h;
    const int qrow0 = qb * 128;

    if (tid == 0) s_anyg = 0;
    __syncthreads();
    {
        int myid = ids[b * T + qrow0 + tid];
        bool myg = false;
        for (int i = 0; i < n_g; i++) myg |= (myid == (int)gidx[i]);
        if (myg) s_anyg = 1;
    }
    unsigned gmask;
    {
        int rid = ids[b * T + qrow0 + w * 32 + lane];
        bool rg = false;
        for (int i = 0; i < n_g; i++) rg |= (rid == (int)gidx[i]);
        gmask = __ballot_sync(0xffffffffu, rg);
    }
    __syncthreads();
    const int ktmax = s_anyg ? (T / 64 - 1) : (2 * qb + 1);

    float q[2][8][4];
    {
        const float* Qb = g_q + ((size_t)bh * T + qrow0 + w * 32) * HDIM;
#pragma unroll
        for (int rb = 0; rb < 2; rb++)
#pragma unroll
            for (int ks = 0; ks < 8; ks++) {
                q[rb][ks][0] = f2tf32f(Qb[(rb * 16 + g) * 64 + ks * 8 + t]);
                q[rb][ks][1] = f2tf32f(Qb[(rb * 16 + 8 + g) * 64 + ks * 8 + t]);
                q[rb][ks][2] = f2tf32f(Qb[(rb * 16 + g) * 64 + ks * 8 + t + 4]);
                q[rb][ks][3] = f2tf32f(Qb[(rb * 16 + 8 + g) * 64 + ks * 8 + t + 4]);
            }
    }

    float o[2][8][4];
#pragma unroll
    for (int rb = 0; rb < 2; rb++)
#pragma unroll
        for (int f = 0; f < 8; f++)
#pragma unroll
            for (int e = 0; e < 4; e++) o[rb][f][e] = 0.f;
    float m_[2][2], l_[2][2];
#pragma unroll
    for (int rb = 0; rb < 2; rb++)
#pragma unroll
        for (int hh = 0; hh < 2; hh++) { m_[rb][hh] = -1e30f; l_[rb][hh] = 0.f; }

    const float* Kgb = g_k + (size_t)bh * T * HDIM;
    const float* Vgb = g_v + (size_t)bh * T * HDIM;

    for (int kt = 0; kt <= ktmax; kt++) {
        __syncthreads();
#pragma unroll
        for (int j = 0; j < 8; j++) {
            int i = tid + j * 128;
            int r = i >> 4;
            int c4 = i & 15;
            float4 kv = *(const float4*)(Kgb + (size_t)(kt * 64 + r) * 64 + c4 * 4);
            float4 vv = *(const float4*)(Vgb + (size_t)(kt * 64 + r) * 64 + c4 * 4);
            float* kp = Ksm + r * KPAD + c4 * 4;
            kp[0] = f2tf32f(kv.x); kp[1] = f2tf32f(kv.y); kp[2] = f2tf32f(kv.z); kp[3] = f2tf32f(kv.w);
            float* vp = Vsm + r * VPAD + c4 * 4;
            vp[0] = f2tf32f(vv.x); vp[1] = f2tf32f(vv.y); vp[2] = f2tf32f(vv.z); vp[3] = f2tf32f(vv.w);
        }
        __syncthreads();

        float s[2][8][4];
#pragma unroll
        for (int rb = 0; rb < 2; rb++)
#pragma unroll
            for (int f = 0; f < 8; f++)
#pragma unroll
                for (int e = 0; e < 4; e++) s[rb][f][e] = 0.f;
#pragma unroll
        for (int ks = 0; ks < 8; ks++) {
#pragma unroll
            for (int f = 0; f < 8; f++) {
                float b0 = Ksm[(f * 8 + g) * KPAD + ks * 8 + t];
                float b1 = Ksm[(f * 8 + g) * KPAD + ks * 8 + t + 4];
                mma_tf32(s[0][f], q[0][ks], b0, b1);
                mma_tf32(s[1][f], q[1][ks], b0, b1);
            }
        }

#pragma unroll
        for (int rb = 0; rb < 2; rb++) {
#pragma unroll
            for (int hh = 0; hh < 2; hh++) {
                const int rloc = rb * 16 + hh * 8 + g;
                const int grow = qrow0 + w * 32 + rloc;
                const bool rowg = (gmask >> rloc) & 1u;
                float pv[16];
                float mx = -1e30f;
                const bool fullok = (kt * 64 + 63 <= grow) || rowg;
#pragma unroll
                for (int f = 0; f < 8; f++) {
#pragma unroll
                    for (int e = 0; e < 2; e++) {
                        float sv = s[rb][f][hh * 2 + e] * 0.125f;
                        if (!fullok) {
                            int col = kt * 64 + f * 8 + 2 * t + e;
                            if (col > grow) sv = -1e30f;
                        }
                        pv[f * 2 + e] = sv;
                        mx = fmaxf(mx, sv);
                    }
                }
                mx = fmaxf(mx, __shfl_xor_sync(0xffffffffu, mx, 1));
                mx = fmaxf(mx, __shfl_xor_sync(0xffffffffu, mx, 2));
                float mold = m_[rb][hh];
                float mnew = fmaxf(mold, mx);
                float corr = __expf(mold - mnew);
                float lsum = 0.f;
#pragma unroll
                for (int i = 0; i < 16; i++) {
                    float p = __expf(pv[i] - mnew);
                    pv[i] = p;
                    lsum += p;
                }
                lsum += __shfl_xor_sync(0xffffffffu, lsum, 1);
                lsum += __shfl_xor_sync(0xffffffffu, lsum, 2);
                m_[rb][hh] = mnew;
                l_[rb][hh] = l_[rb][hh] * corr + lsum;
#pragma unroll
                for (int f = 0; f < 8; f++) {
                    o[rb][f][hh * 2] *= corr;
                    o[rb][f][hh * 2 + 1] *= corr;
                }
                float* prow = Psm + w * (32 * PPAD) + rloc * PPAD;
#pragma unroll
                for (int f = 0; f < 8; f++) {
                    float2 pr;
                    pr.x = f2tf32f(pv[f * 2]);
                    pr.y = f2tf32f(pv[f * 2 + 1]);
                    *(float2*)(prow + f * 8 + 2 * t) = pr;
                }
            }
        }
        __syncwarp();

        const float* pb = Psm + w * (32 * PPAD);
#pragma unroll
        for (int ks = 0; ks < 8; ks++) {
            float ap[2][4];
#pragma unroll
            for (int rb = 0; rb < 2; rb++) {
                ap[rb][0] = pb[(rb * 16 + g) * PPAD + ks * 8 + t];
                ap[rb][1] = pb[(rb * 16 + 8 + g) * PPAD + ks * 8 + t];
                ap[rb][2] = pb[(rb * 16 + g) * PPAD + ks * 8 + t + 4];
                ap[rb][3] = pb[(rb * 16 + 8 + g) * PPAD + ks * 8 + t + 4];
            }
#pragma unroll
            for (int f = 0; f < 8; f++) {
                float b0 = Vsm[(ks * 8 + t) * VPAD + f * 8 + g];
                float b1 = Vsm[(ks * 8 + t + 4) * VPAD + f * 8 + g];
                mma_tf32(o[0][f], ap[0], b0, b1);
                mma_tf32(o[1][f], ap[1], b0, b1);
            }
        }
    }

    // epilogue: normalize, tf32-round (out-proj input), write
#pragma unroll
    for (int rb = 0; rb < 2; rb++) {
#pragma unroll
        for (int hh = 0; hh < 2; hh++) {
            float invl = 1.0f / l_[rb][hh];
            int trow = qrow0 + w * 32 + rb * 16 + hh * 8 + g;
            float* op = g_ctx + ((size_t)b * T + trow) * HIDDEN + h * 64;
#pragma unroll
            for (int f = 0; f < 8; f++) {
                float2 r;
                r.x = f2tf32f(o[rb][f][hh * 2] * invl);
                r.y = f2tf32f(o[rb][f][hh * 2 + 1] * invl);
                *(float2*)(op + f * 8 + 2 * t) = r;
            }
        }
    }
}

// ---------------- host launch ------------------------------------------------
extern "C" void kernel_launch(void* const* d_in, const int* in_sizes, int n_in,
                              void* d_out, int out_size)
{
    const float* x      = (const float*)d_in[0];
    const int*   ids    = (const int*)d_in[1];
    const float* qkv_w  = (const float*)d_in[2];
    const float* qkv_b  = (const float*)d_in[3];
    const float* out_w  = (const float*)d_in[4];
    const float* out_b  = (const float*)d_in[5];
    const long long* gi = (const long long*)d_in[6];
    const int n_g = in_sizes[6];
    float* out = (float*)d_out;

    float *p_qkv, *p_ctx, *p_xr, *p_wqkv, *p_wout;
    cudaGetSymbolAddress((void**)&p_qkv, g_qkv);
    cudaGetSymbolAddress((void**)&p_ctx, g_ctx);
    cudaGetSymbolAddress((void**)&p_xr, g_xr);
    cudaGetSymbolAddress((void**)&p_wqkv, g_wqkv);
    cudaGetSymbolAddress((void**)&p_wout, g_wout);

    cudaFuncSetAttribute(mma_gemm,
                         cudaFuncAttributeMaxDynamicSharedMemorySize, TSM_BYTES);
    cudaFuncSetAttribute(flash_mma,
                         cudaFuncAttributeMaxDynamicSharedMemorySize, FSM_BYTES);

    // 0) pre-round inputs to tf32 (cp.async path cannot round; truncation is biased)
    round_tf32<<<(BT * HIDDEN / 4 + 255) / 256, 256>>>(x, p_xr, BT * HIDDEN / 4);
    round_tf32<<<(QKV3 * HIDDEN / 4 + 255) / 256, 256>>>(qkv_w, p_wqkv, QKV3 * HIDDEN / 4);
    round_tf32<<<(HIDDEN * HIDDEN / 4 + 255) / 256, 256>>>(out_w, p_wout, HIDDEN * HIDDEN / 4);

    // 1) QKV projection
    {
        dim3 grid(QKV3 / 128, BT / 128);
        mma_gemm<<<grid, 256, TSM_BYTES>>>(p_xr, p_wqkv, qkv_b, p_qkv, QKV3, HIDDEN);
    }
    // 2) RoPE + reshape
    {
        int total = B * T * HEADS * 32;
        rope_reshape<<<(total + 255) / 256, 256>>>(p_qkv);
    }
    // 3) Flash attention (tensor cores)
    {
        dim3 grid(T / 128, HEADS, B);
        flash_mma<<<grid, 128, FSM_BYTES>>>(ids, gi, n_g);
    }
    // 4) Output projection
    {
        dim3 grid(HIDDEN / 128, BT / 128);
        mma_gemm<<<grid, 256, TSM_BYTES>>>(p_ctx, p_wout, out_b, out, HIDDEN, HIDDEN);
    }
}

// round 8
// speedup vs baseline: 4.0454x; 1.1079x over previous
#include <cuda_runtime.h>
#include <cuda_bf16.h>
#include <stdint.h>
#include <float.h>
#include <math.h>

// Problem constants
#define HIDDEN 1024
#define HEADS  16
#define HDIM   64
#define B      2
#define T      2048
#define QKV3   (3 * HIDDEN)
#define BT     (B * T)        // 4096

// ---------------- scratch (static device globals; no allocation) -------------
__device__ float g_qkv[(size_t)BT * QKV3];                 // 4096 x 3072
__device__ float g_q[(size_t)B * HEADS * T * HDIM];        // [b,h,t,d]
__device__ float g_k[(size_t)B * HEADS * T * HDIM];
__device__ float g_v[(size_t)B * HEADS * T * HDIM];
__device__ float g_ctx[(size_t)BT * HIDDEN];               // [b,t,hidden] K-permuted + tf32
__device__ float g_xr[(size_t)BT * HIDDEN];                // tf32 + K-permuted x
__device__ float g_wqkv[(size_t)QKV3 * HIDDEN];            // tf32 + K-permuted qkv_w
__device__ float g_wout[(size_t)HIDDEN * HIDDEN];          // tf32 + K-permuted out_w

__device__ __forceinline__ float f2tf32f(float x) {
    uint32_t u;
    asm("cvt.rna.tf32.f32 %0, %1;" : "=r"(u) : "f"(x));
    return __uint_as_float(u);
}

__device__ __forceinline__ uint32_t smem_u32(const void* p) {
    uint32_t a;
    asm("{ .reg .u64 t; cvta.to.shared.u64 t, %1; cvt.u32.u64 %0, t; }"
        : "=r"(a) : "l"(p));
    return a;
}

#define CP_ASYNC16(dst, src) \
    asm volatile("cp.async.ca.shared.global [%0], [%1], 16;" :: "r"(dst), "l"(src))
#define CP_COMMIT() asm volatile("cp.async.commit_group;" ::: "memory")
#define CP_WAIT0() asm volatile("cp.async.wait_group 0;" ::: "memory")
#define CP_WAIT1() asm volatile("cp.async.wait_group 1;" ::: "memory")

// raw tf32 mma: D(16x8) += A(16x8) * B(8x8); acc regs in-place
__device__ __forceinline__ void mma_tf32(float* c, const float* a, float b0, float b1) {
    asm volatile(
        "mma.sync.aligned.m16n8k8.row.col.f32.tf32.tf32.f32 "
        "{%0,%1,%2,%3}, {%4,%5,%6,%7}, {%8,%9}, {%0,%1,%2,%3};"
        : "+f"(c[0]), "+f"(c[1]), "+f"(c[2]), "+f"(c[3])
        : "r"(__float_as_uint(a[0])), "r"(__float_as_uint(a[1])),
          "r"(__float_as_uint(a[2])), "r"(__float_as_uint(a[3])),
          "r"(__float_as_uint(b0)), "r"(__float_as_uint(b1)));
}

// -------- tf32 round + K-pair permute: within each 8-group, new[2j]=old[j],
// new[2j+1]=old[j+4]  (so cols (t, t+4) are adjacent -> float2 frag loads) ----
__global__ void round_perm_tf32(const float* __restrict__ src, float* __restrict__ dst, int n8)
{
    int i = blockIdx.x * blockDim.x + threadIdx.x;
    if (i >= n8) return;
    float4 a = ((const float4*)src)[i * 2];
    float4 b = ((const float4*)src)[i * 2 + 1];
    float4 o0, o1;
    o0.x = f2tf32f(a.x); o0.y = f2tf32f(b.x); o0.z = f2tf32f(a.y); o0.w = f2tf32f(b.y);
    o1.x = f2tf32f(a.z); o1.y = f2tf32f(b.z); o1.z = f2tf32f(a.w); o1.w = f2tf32f(b.w);
    ((float4*)dst)[i * 2] = o0;
    ((float4*)dst)[i * 2 + 1] = o1;
}

// ========= raw-mma TF32 GEMM v2: C[M,N] = A[M,K] @ W[N,K]^T + bias ===========
// Inputs pre-rounded + K-permuted. CTA 128x256, 8 warps (warp 64x64),
// BK=32 chunks, 3-stage cp.async, frag double-buffer, one sync per chunk.
#define BKC 32
#define ASTR 40
#define STG_A (128 * ASTR)
#define STG_B (256 * ASTR)
#define STG_F (STG_A + STG_B)          // floats per stage
#define NSTG 3
#define TSM_BYTES (NSTG * STG_F * 4)   // 184320

__global__ __launch_bounds__(256, 1) void mma_gemm(
    const float* __restrict__ A, const float* __restrict__ W,
    const float* __restrict__ bias, float* __restrict__ C,
    int Nt, int K)
{
    extern __shared__ float sm[];
    const int tid = threadIdx.x;
    const int wid = tid >> 5;
    const int lane = tid & 31;
    const int g = lane >> 2;
    const int t = lane & 3;
    const int bm = blockIdx.y * 128;
    const int bn = blockIdx.x * 256;
    const int warpM = wid & 1;        // 0..1 -> 64-row slab
    const int warpN = wid >> 1;       // 0..3 -> 64-col slab

    // loader: thread i -> row lrow = i>>1, half h = i&1; quads rotated by row
    const int lrow = tid >> 1;
    const int lh = tid & 1;
    const uint32_t sb = smem_u32(sm);
    const float* gA = A + (size_t)(bm + lrow) * K;
    const float* gW0 = W + (size_t)(bn + lrow) * K;
    const float* gW1 = W + (size_t)(bn + 128 + lrow) * K;

    float acc[4][8][4];
#pragma unroll
    for (int mi = 0; mi < 4; mi++)
#pragma unroll
        for (int ni = 0; ni < 8; ni++)
#pragma unroll
            for (int e = 0; e < 4; e++) acc[mi][ni][e] = 0.f;

    const int NC = K / BKC;

    // chunk issue: 12 cp.async per thread
#define ISSUE_CHUNK(c)                                                          \
    do {                                                                        \
        const uint32_t base = sb + ((c) % NSTG) * (STG_F * 4);                  \
        const int k0 = (c) * BKC;                                               \
        _Pragma("unroll")                                                       \
        for (int q = 0; q < 4; q++) {                                           \
            const int qa = (q + lrow) & 3;                                      \
            const int col = 16 * lh + 4 * qa;                                   \
            CP_ASYNC16(base + (lrow * ASTR + col) * 4, gA + k0 + col);          \
            CP_ASYNC16(base + (STG_A + lrow * ASTR + col) * 4, gW0 + k0 + col); \
            CP_ASYNC16(base + (STG_A + (128 + lrow) * ASTR + col) * 4, gW1 + k0 + col); \
        }                                                                       \
        CP_COMMIT();                                                            \
    } while (0)

    ISSUE_CHUNK(0);
    ISSUE_CHUNK(1);

    for (int c = 0; c < NC; c++) {
        if (c + 1 < NC) CP_WAIT1(); else CP_WAIT0();
        __syncthreads();
        if (c + 2 < NC) ISSUE_CHUNK(c + 2);

        const float* Ab = sm + (c % NSTG) * STG_F + (warpM * 64) * ASTR;
        const float* Wb = sm + (c % NSTG) * STG_F + STG_A + (warpN * 64) * ASTR;

        float af[2][4][4], bf[2][8][2];
        // load frags ks=0 into buf 0
#pragma unroll
        for (int mi = 0; mi < 4; mi++) {
            float2 lo = *(const float2*)(Ab + (mi * 16 + g) * ASTR + 2 * t);
            float2 hi = *(const float2*)(Ab + (mi * 16 + 8 + g) * ASTR + 2 * t);
            af[0][mi][0] = lo.x; af[0][mi][1] = hi.x; af[0][mi][2] = lo.y; af[0][mi][3] = hi.y;
        }
#pragma unroll
        for (int ni = 0; ni < 8; ni++) {
            float2 bv = *(const float2*)(Wb + (ni * 8 + g) * ASTR + 2 * t);
            bf[0][ni][0] = bv.x; bf[0][ni][1] = bv.y;
        }
#pragma unroll
        for (int ks = 0; ks < 4; ks++) {
            const int cur = ks & 1;
            if (ks < 3) {
                const int nxt = cur ^ 1;
                const int kc = (ks + 1) * 8;
#pragma unroll
                for (int mi = 0; mi < 4; mi++) {
                    float2 lo = *(const float2*)(Ab + (mi * 16 + g) * ASTR + kc + 2 * t);
                    float2 hi = *(const float2*)(Ab + (mi * 16 + 8 + g) * ASTR + kc + 2 * t);
                    af[nxt][mi][0] = lo.x; af[nxt][mi][1] = hi.x;
                    af[nxt][mi][2] = lo.y; af[nxt][mi][3] = hi.y;
                }
#pragma unroll
                for (int ni = 0; ni < 8; ni++) {
                    float2 bv = *(const float2*)(Wb + (ni * 8 + g) * ASTR + kc + 2 * t);
                    bf[nxt][ni][0] = bv.x; bf[nxt][ni][1] = bv.y;
                }
            }
#pragma unroll
            for (int mi = 0; mi < 4; mi++)
#pragma unroll
                for (int ni = 0; ni < 8; ni++)
                    mma_tf32(acc[mi][ni], af[cur][mi], bf[cur][ni][0], bf[cur][ni][1]);
        }
    }

    // epilogue: float2 stores + bias
#pragma unroll
    for (int mi = 0; mi < 4; mi++) {
        const int row0 = bm + warpM * 64 + mi * 16 + g;
#pragma unroll
        for (int ni = 0; ni < 8; ni++) {
            const int col = bn + warpN * 64 + ni * 8 + 2 * t;
            const float bx = bias[col], by = bias[col + 1];
            float2 r0, r1;
            r0.x = acc[mi][ni][0] + bx; r0.y = acc[mi][ni][1] + by;
            r1.x = acc[mi][ni][2] + bx; r1.y = acc[mi][ni][3] + by;
            *(float2*)(C + (size_t)row0 * Nt + col) = r0;
            *(float2*)(C + (size_t)(row0 + 8) * Nt + col) = r1;
        }
    }
#undef ISSUE_CHUNK
}

// ---------------- RoPE + reshape into [b,h,t,d] ------------------------------
__global__ void rope_reshape(const float* __restrict__ qkv)
{
    int tid = blockIdx.x * blockDim.x + threadIdx.x;
    const int total = B * T * HEADS * 32;
    if (tid >= total) return;
    int i = tid & 31;
    int h = (tid >> 5) & (HEADS - 1);
    int t = (tid >> 9) & (T - 1);
    int b = tid >> 20;

    const float expo = (float)(2 * i) / 64.0f;
    const float inv = 1.0f / powf(10000.0f, expo);
    const float ang = (float)t * inv;
    float c = cosf(ang), s = sinf(ang);

    const size_t base = (size_t)(b * T + t) * QKV3;
    const size_t ob = ((size_t)(b * HEADS + h) * T + t) * HDIM;

    float q1 = qkv[base + h * HDIM + i];
    float q2 = qkv[base + h * HDIM + i + 32];
    g_q[ob + i]      = q1 * c - q2 * s;
    g_q[ob + i + 32] = q1 * s + q2 * c;

    float k1 = qkv[base + HIDDEN + h * HDIM + i];
    float k2 = qkv[base + HIDDEN + h * HDIM + i + 32];
    g_k[ob + i]      = k1 * c - k2 * s;
    g_k[ob + i + 32] = k1 * s + k2 * c;

    g_v[ob + i]      = qkv[base + 2 * HIDDEN + h * HDIM + i];
    g_v[ob + i + 32] = qkv[base + 2 * HIDDEN + h * HDIM + i + 32];
}

// ================== tensor-core flash attention ==============================
#define KPAD 68
#define VPAD 72
#define PPAD 68
#define FSM_K 0
#define FSM_V (64 * KPAD)
#define FSM_P (FSM_V + 64 * VPAD)
#define FSM_FLOATS (FSM_P + 4 * 32 * PPAD)
#define FSM_BYTES (FSM_FLOATS * 4)

__global__ __launch_bounds__(128) void flash_mma(
    const int* __restrict__ ids, const long long* __restrict__ gidx, int n_g)
{
    extern __shared__ float fsm[];
    float* Ksm = fsm + FSM_K;
    float* Vsm = fsm + FSM_V;
    float* Psm = fsm + FSM_P;
    __shared__ int s_anyg;

    const int tid = threadIdx.x;
    const int w = tid >> 5;
    const int lane = tid & 31;
    const int g = lane >> 2;
    const int t = lane & 3;
    const int qb = blockIdx.x;
    const int h = blockIdx.y;
    const int b = blockIdx.z;
    const int bh = b * HEADS + h;
    const int qrow0 = qb * 128;

    if (tid == 0) s_anyg = 0;
    __syncthreads();
    {
        int myid = ids[b * T + qrow0 + tid];
        bool myg = false;
        for (int i = 0; i < n_g; i++) myg |= (myid == (int)gidx[i]);
        if (myg) s_anyg = 1;
    }
    unsigned gmask;
    {
        int rid = ids[b * T + qrow0 + w * 32 + lane];
        bool rg = false;
        for (int i = 0; i < n_g; i++) rg |= (rid == (int)gidx[i]);
        gmask = __ballot_sync(0xffffffffu, rg);
    }
    __syncthreads();
    const int ktmax = s_anyg ? (T / 64 - 1) : (2 * qb + 1);

    float q[2][8][4];
    {
        const float* Qb = g_q + ((size_t)bh * T + qrow0 + w * 32) * HDIM;
#pragma unroll
        for (int rb = 0; rb < 2; rb++)
#pragma unroll
            for (int ks = 0; ks < 8; ks++) {
                q[rb][ks][0] = f2tf32f(Qb[(rb * 16 + g) * 64 + ks * 8 + t]);
                q[rb][ks][1] = f2tf32f(Qb[(rb * 16 + 8 + g) * 64 + ks * 8 + t]);
                q[rb][ks][2] = f2tf32f(Qb[(rb * 16 + g) * 64 + ks * 8 + t + 4]);
                q[rb][ks][3] = f2tf32f(Qb[(rb * 16 + 8 + g) * 64 + ks * 8 + t + 4]);
            }
    }

    float o[2][8][4];
#pragma unroll
    for (int rb = 0; rb < 2; rb++)
#pragma unroll
        for (int f = 0; f < 8; f++)
#pragma unroll
            for (int e = 0; e < 4; e++) o[rb][f][e] = 0.f;
    float m_[2][2], l_[2][2];
#pragma unroll
    for (int rb = 0; rb < 2; rb++)
#pragma unroll
        for (int hh = 0; hh < 2; hh++) { m_[rb][hh] = -1e30f; l_[rb][hh] = 0.f; }

    const float* Kgb = g_k + (size_t)bh * T * HDIM;
    const float* Vgb = g_v + (size_t)bh * T * HDIM;

    for (int kt = 0; kt <= ktmax; kt++) {
        __syncthreads();
#pragma unroll
        for (int j = 0; j < 8; j++) {
            int i = tid + j * 128;
            int r = i >> 4;
            int c4 = i & 15;
            float4 kv = *(const float4*)(Kgb + (size_t)(kt * 64 + r) * 64 + c4 * 4);
            float4 vv = *(const float4*)(Vgb + (size_t)(kt * 64 + r) * 64 + c4 * 4);
            float* kp = Ksm + r * KPAD + c4 * 4;
            kp[0] = f2tf32f(kv.x); kp[1] = f2tf32f(kv.y); kp[2] = f2tf32f(kv.z); kp[3] = f2tf32f(kv.w);
            float* vp = Vsm + r * VPAD + c4 * 4;
            vp[0] = f2tf32f(vv.x); vp[1] = f2tf32f(vv.y); vp[2] = f2tf32f(vv.z); vp[3] = f2tf32f(vv.w);
        }
        __syncthreads();

        float s[2][8][4];
#pragma unroll
        for (int rb = 0; rb < 2; rb++)
#pragma unroll
            for (int f = 0; f < 8; f++)
#pragma unroll
                for (int e = 0; e < 4; e++) s[rb][f][e] = 0.f;
#pragma unroll
        for (int ks = 0; ks < 8; ks++) {
#pragma unroll
            for (int f = 0; f < 8; f++) {
                float b0 = Ksm[(f * 8 + g) * KPAD + ks * 8 + t];
                float b1 = Ksm[(f * 8 + g) * KPAD + ks * 8 + t + 4];
                mma_tf32(s[0][f], q[0][ks], b0, b1);
                mma_tf32(s[1][f], q[1][ks], b0, b1);
            }
        }

#pragma unroll
        for (int rb = 0; rb < 2; rb++) {
#pragma unroll
            for (int hh = 0; hh < 2; hh++) {
                const int rloc = rb * 16 + hh * 8 + g;
                const int grow = qrow0 + w * 32 + rloc;
                const bool rowg = (gmask >> rloc) & 1u;
                float pv[16];
                float mx = -1e30f;
                const bool fullok = (kt * 64 + 63 <= grow) || rowg;
#pragma unroll
                for (int f = 0; f < 8; f++) {
#pragma unroll
                    for (int e = 0; e < 2; e++) {
                        float sv = s[rb][f][hh * 2 + e] * 0.125f;
                        if (!fullok) {
                            int col = kt * 64 + f * 8 + 2 * t + e;
                            if (col > grow) sv = -1e30f;
                        }
                        pv[f * 2 + e] = sv;
                        mx = fmaxf(mx, sv);
                    }
                }
                mx = fmaxf(mx, __shfl_xor_sync(0xffffffffu, mx, 1));
                mx = fmaxf(mx, __shfl_xor_sync(0xffffffffu, mx, 2));
                float mold = m_[rb][hh];
                float mnew = fmaxf(mold, mx);
                float corr = __expf(mold - mnew);
                float lsum = 0.f;
#pragma unroll
                for (int i = 0; i < 16; i++) {
                    float p = __expf(pv[i] - mnew);
                    pv[i] = p;
                    lsum += p;
                }
                lsum += __shfl_xor_sync(0xffffffffu, lsum, 1);
                lsum += __shfl_xor_sync(0xffffffffu, lsum, 2);
                m_[rb][hh] = mnew;
                l_[rb][hh] = l_[rb][hh] * corr + lsum;
#pragma unroll
                for (int f = 0; f < 8; f++) {
                    o[rb][f][hh * 2] *= corr;
                    o[rb][f][hh * 2 + 1] *= corr;
                }
                float* prow = Psm + w * (32 * PPAD) + rloc * PPAD;
#pragma unroll
                for (int f = 0; f < 8; f++) {
                    float2 pr;
                    pr.x = f2tf32f(pv[f * 2]);
                    pr.y = f2tf32f(pv[f * 2 + 1]);
                    *(float2*)(prow + f * 8 + 2 * t) = pr;
                }
            }
        }
        __syncwarp();

        const float* pb = Psm + w * (32 * PPAD);
#pragma unroll
        for (int ks = 0; ks < 8; ks++) {
            float ap[2][4];
#pragma unroll
            for (int rb = 0; rb < 2; rb++) {
                ap[rb][0] = pb[(rb * 16 + g) * PPAD + ks * 8 + t];
                ap[rb][1] = pb[(rb * 16 + 8 + g) * PPAD + ks * 8 + t];
                ap[rb][2] = pb[(rb * 16 + g) * PPAD + ks * 8 + t + 4];
                ap[rb][3] = pb[(rb * 16 + 8 + g) * PPAD + ks * 8 + t + 4];
            }
#pragma unroll
            for (int f = 0; f < 8; f++) {
                float b0 = Vsm[(ks * 8 + t) * VPAD + f * 8 + g];
                float b1 = Vsm[(ks * 8 + t + 4) * VPAD + f * 8 + g];
                mma_tf32(o[0][f], ap[0], b0, b1);
                mma_tf32(o[1][f], ap[1], b0, b1);
            }
        }
    }

    // epilogue: normalize, tf32-round, write K-PERMUTED ctx (out-proj input):
    // within each 8-group, old col j -> (j<4 ? 2j : 2(j-4)+1)
#pragma unroll
    for (int rb = 0; rb < 2; rb++) {
#pragma unroll
        for (int hh = 0; hh < 2; hh++) {
            float invl = 1.0f / l_[rb][hh];
            int trow = qrow0 + w * 32 + rb * 16 + hh * 8 + g;
            float* op = g_ctx + ((size_t)b * T + trow) * HIDDEN + h * 64;
            const int c0 = (t < 2) ? (4 * t) : (4 * t - 7);
#pragma unroll
            for (int f = 0; f < 8; f++) {
                op[f * 8 + c0]     = f2tf32f(o[rb][f][hh * 2] * invl);
                op[f * 8 + c0 + 2] = f2tf32f(o[rb][f][hh * 2 + 1] * invl);
            }
        }
    }
}

// ---------------- host launch ------------------------------------------------
extern "C" void kernel_launch(void* const* d_in, const int* in_sizes, int n_in,
                              void* d_out, int out_size)
{
    const float* x      = (const float*)d_in[0];
    const int*   ids    = (const int*)d_in[1];
    const float* qkv_w  = (const float*)d_in[2];
    const float* qkv_b  = (const float*)d_in[3];
    const float* out_w  = (const float*)d_in[4];
    const float* out_b  = (const float*)d_in[5];
    const long long* gi = (const long long*)d_in[6];
    const int n_g = in_sizes[6];
    float* out = (float*)d_out;

    float *p_qkv, *p_ctx, *p_xr, *p_wqkv, *p_wout;
    cudaGetSymbolAddress((void**)&p_qkv, g_qkv);
    cudaGetSymbolAddress((void**)&p_ctx, g_ctx);
    cudaGetSymbolAddress((void**)&p_xr, g_xr);
    cudaGetSymbolAddress((void**)&p_wqkv, g_wqkv);
    cudaGetSymbolAddress((void**)&p_wout, g_wout);

    cudaFuncSetAttribute(mma_gemm,
                         cudaFuncAttributeMaxDynamicSharedMemorySize, TSM_BYTES);
    cudaFuncSetAttribute(flash_mma,
                         cudaFuncAttributeMaxDynamicSharedMemorySize, FSM_BYTES);

    // 0) round + K-permute operands
    round_perm_tf32<<<(BT * HIDDEN / 8 + 255) / 256, 256>>>(x, p_xr, BT * HIDDEN / 8);
    round_perm_tf32<<<(QKV3 * HIDDEN / 8 + 255) / 256, 256>>>(qkv_w, p_wqkv, QKV3 * HIDDEN / 8);
    round_perm_tf32<<<(HIDDEN * HIDDEN / 8 + 255) / 256, 256>>>(out_w, p_wout, HIDDEN * HIDDEN / 8);

    // 1) QKV projection
    {
        dim3 grid(QKV3 / 256, BT / 128);
        mma_gemm<<<grid, 256, TSM_BYTES>>>(p_xr, p_wqkv, qkv_b, p_qkv, QKV3, HIDDEN);
    }
    // 2) RoPE + reshape
    {
        int total = B * T * HEADS * 32;
        rope_reshape<<<(total + 255) / 256, 256>>>(p_qkv);
    }
    // 3) Flash attention (tensor cores)
    {
        dim3 grid(T / 128, HEADS, B);
        flash_mma<<<grid, 128, FSM_BYTES>>>(ids, gi, n_g);
    }
    // 4) Output projection
    {
        dim3 grid(HIDDEN / 256, BT / 128);
        mma_gemm<<<grid, 256, TSM_BYTES>>>(p_ctx, p_wout, out_b, out, HIDDEN, HIDDEN);
    }
}